// round 1
// baseline (speedup 1.0000x reference)
#include <cuda_runtime.h>

// Problem constants
#define Bb   2
#define Ss   2048
#define Hh   2048
#define NHh  16
#define HDim 128
#define BS   4096          // Bb*Ss

// Scratch (device globals: allocation-free, graph-capture safe)
__device__ float g_Wqc[4194304];    // H*H combined W_q @ W_q_m
__device__ float g_Wkc[4194304];
__device__ float g_Wvc[4194304];
__device__ float g_Qm[8388608];     // BS*H
__device__ float g_Km[8388608];
__device__ float g_Vm[8388608];
__device__ float g_Sc[134217728];   // B*NH*S*S attention scores/weights
__device__ float g_Att[8388608];    // BS*H attention output

// ---------------------------------------------------------------------------
// SGEMM: C = A @ B  (TRANS_B=0: B is [K,N] row-major; TRANS_B=1: B is [N,K])
// 128x128 tile, BK=8, 256 threads, 8x8 per thread, float4 loads.
// All dims are multiples of tile sizes for this problem (no bounds checks).
// blockIdx.z batches with the given strides.
// ---------------------------------------------------------------------------
template <int TRANS_B>
__global__ void __launch_bounds__(256, 2)
sgemm(const float* __restrict__ Ag, const float* __restrict__ Bg,
      float* __restrict__ Cg, int M, int N, int K,
      long sA, long sB, long sC)
{
    constexpr int BM = 128, BN = 128, BK = 8;
    __shared__ float As[BK][BM];
    __shared__ float Bs[BK][BN];

    const float* A = Ag + (long)blockIdx.z * sA;
    const float* B = Bg + (long)blockIdx.z * sB;
    float*       C = Cg + (long)blockIdx.z * sC;

    const int tid = threadIdx.x;
    const int tx  = tid & 15;          // 0..15 -> 8 cols each
    const int ty  = tid >> 4;          // 0..15 -> 8 rows each
    const int rowBase = blockIdx.y * BM;
    const int colBase = blockIdx.x * BN;

    // load mapping
    const int aRow = tid >> 1;               // 0..127
    const int aCol = (tid & 1) << 2;         // 0 or 4 (k offset)
    const int bR   = TRANS_B ? (tid >> 1) : (tid >> 5);
    const int bC   = TRANS_B ? ((tid & 1) << 2) : ((tid & 31) << 2);

    float acc[8][8];
#pragma unroll
    for (int i = 0; i < 8; i++)
#pragma unroll
        for (int j = 0; j < 8; j++) acc[i][j] = 0.0f;

    const float* Aptr = A + (long)(rowBase + aRow) * K + aCol;
    const float* Bptr = TRANS_B ? (B + (long)(colBase + bR) * K + bC)
                                : (B + (long)bR * N + colBase + bC);

    for (int k0 = 0; k0 < K; k0 += BK) {
        float4 av = *(const float4*)(Aptr + k0);
        As[aCol + 0][aRow] = av.x;
        As[aCol + 1][aRow] = av.y;
        As[aCol + 2][aRow] = av.z;
        As[aCol + 3][aRow] = av.w;
        if (TRANS_B) {
            float4 bv = *(const float4*)(Bptr + k0);
            Bs[bC + 0][bR] = bv.x;
            Bs[bC + 1][bR] = bv.y;
            Bs[bC + 2][bR] = bv.z;
            Bs[bC + 3][bR] = bv.w;
        } else {
            float4 bv = *(const float4*)(Bptr + (long)k0 * N);
            *(float4*)&Bs[bR][bC] = bv;
        }
        __syncthreads();
#pragma unroll
        for (int kk = 0; kk < BK; kk++) {
            float a[8], b[8];
            *(float4*)(a)     = *(const float4*)&As[kk][ty * 8];
            *(float4*)(a + 4) = *(const float4*)&As[kk][ty * 8 + 4];
            *(float4*)(b)     = *(const float4*)&Bs[kk][tx * 8];
            *(float4*)(b + 4) = *(const float4*)&Bs[kk][tx * 8 + 4];
#pragma unroll
            for (int i = 0; i < 8; i++)
#pragma unroll
                for (int j = 0; j < 8; j++)
                    acc[i][j] = fmaf(a[i], b[j], acc[i][j]);
        }
        __syncthreads();
    }

#pragma unroll
    for (int i = 0; i < 8; i++) {
        float* crow = C + (long)(rowBase + ty * 8 + i) * N + colBase + tx * 8;
        *(float4*)(crow)     = make_float4(acc[i][0], acc[i][1], acc[i][2], acc[i][3]);
        *(float4*)(crow + 4) = make_float4(acc[i][4], acc[i][5], acc[i][6], acc[i][7]);
    }
}

// ---------------------------------------------------------------------------
// Masked softmax over one score row per block (row length Ss=2048, 256 thr).
// Row index r = z*Ss + q with z = b*NH + n. Mask semantics match reference:
// score = NEG if mask[b,q]==0 or mask[b,k]==0; fully-masked rows -> uniform.
// ---------------------------------------------------------------------------
__global__ void __launch_bounds__(256)
masked_softmax(float* __restrict__ scores, const int* __restrict__ mask)
{
    const long r = blockIdx.x;
    const int  q = (int)(r & (Ss - 1));
    const int  z = (int)(r >> 11);          // /Ss
    const int  b = z >> 4;                  // /NH
    float*       row  = scores + r * (long)Ss;
    const int*   mrow = mask + b * Ss;
    const int    mq   = mrow[q];
    const int    tid  = threadIdx.x;

    __shared__ float red_m[8];
    __shared__ float red_s[8];

    float v[8];
    float mx = -3.0e38f;
#pragma unroll
    for (int i = 0; i < 8; i++) {
        const int k = tid + i * 256;
        float s = row[k];
        if (mq == 0 || mrow[k] == 0) s = -1000000.0f;
        v[i] = s;
        mx = fmaxf(mx, s);
    }
#pragma unroll
    for (int o = 16; o > 0; o >>= 1)
        mx = fmaxf(mx, __shfl_xor_sync(0xffffffffu, mx, o));
    if ((tid & 31) == 0) red_m[tid >> 5] = mx;
    __syncthreads();
    mx = red_m[0];
#pragma unroll
    for (int i = 1; i < 8; i++) mx = fmaxf(mx, red_m[i]);

    float sum = 0.0f;
#pragma unroll
    for (int i = 0; i < 8; i++) {
        v[i] = __expf(v[i] - mx);
        sum += v[i];
    }
#pragma unroll
    for (int o = 16; o > 0; o >>= 1)
        sum += __shfl_xor_sync(0xffffffffu, sum, o);
    if ((tid & 31) == 0) red_s[tid >> 5] = sum;
    __syncthreads();
    float tot = red_s[0];
#pragma unroll
    for (int i = 1; i < 8; i++) tot += red_s[i];

    const float inv = 1.0f / tot;
#pragma unroll
    for (int i = 0; i < 8; i++)
        row[tid + i * 256] = v[i] * inv;
}

// ---------------------------------------------------------------------------
extern "C" void kernel_launch(void* const* d_in, const int* in_sizes, int n_in,
                              void* d_out, int out_size)
{
    (void)in_sizes; (void)n_in; (void)out_size;
    const float* X   = (const float*)d_in[0];
    const int*   msk = (const int*)  d_in[1];
    const float* Wq  = (const float*)d_in[2];
    const float* Wk  = (const float*)d_in[3];
    const float* Wv  = (const float*)d_in[4];
    const float* Wqm = (const float*)d_in[5];
    const float* Wkm = (const float*)d_in[6];
    const float* Wvm = (const float*)d_in[7];
    const float* Wo  = (const float*)d_in[8];
    float* Y = (float*)d_out;

    float *Wqc, *Wkc, *Wvc, *Qm, *Km, *Vm, *Sc, *Att;
    cudaGetSymbolAddress((void**)&Wqc, g_Wqc);
    cudaGetSymbolAddress((void**)&Wkc, g_Wkc);
    cudaGetSymbolAddress((void**)&Wvc, g_Wvc);
    cudaGetSymbolAddress((void**)&Qm,  g_Qm);
    cudaGetSymbolAddress((void**)&Km,  g_Km);
    cudaGetSymbolAddress((void**)&Vm,  g_Vm);
    cudaGetSymbolAddress((void**)&Sc,  g_Sc);
    cudaGetSymbolAddress((void**)&Att, g_Att);

    const dim3 blk(256);

    // 1) Combined projection weights: Wc = W @ W_m   [2048x2048]
    const dim3 gW(Hh / 128, Hh / 128, 1);
    sgemm<0><<<gW, blk>>>(Wq, Wqm, Wqc, Hh, Hh, Hh, 0, 0, 0);
    sgemm<0><<<gW, blk>>>(Wk, Wkm, Wkc, Hh, Hh, Hh, 0, 0, 0);
    sgemm<0><<<gW, blk>>>(Wv, Wvm, Wvc, Hh, Hh, Hh, 0, 0, 0);

    // 2) Projections: P = X @ Wc   [4096x2048]
    const dim3 gP(Hh / 128, BS / 128, 1);
    sgemm<0><<<gP, blk>>>(X, Wqc, Qm, BS, Hh, Hh, 0, 0, 0);
    sgemm<0><<<gP, blk>>>(X, Wkc, Km, BS, Hh, Hh, 0, 0, 0);
    sgemm<0><<<gP, blk>>>(X, Wvc, Vm, BS, Hh, Hh, 0, 0, 0);

    // 3) Scores: per z in [0,32): S_z = Qh_z @ Kh_z^T, heads are contiguous
    //    row blocks of the [B*S*16, 128] view of Qm/Km.
    const dim3 gS(Ss / 128, Ss / 128, Bb * NHh);
    sgemm<1><<<gS, blk>>>(Qm, Km, Sc, Ss, Ss, HDim,
                          (long)Ss * HDim, (long)Ss * HDim, (long)Ss * Ss);

    // 4) Masked softmax (in place)
    masked_softmax<<<(unsigned)(Bb * NHh * Ss), blk>>>(Sc, msk);

    // 5) PV: O_z = W_z @ Vh_z   [2048x128]
    const dim3 gV(HDim / 128, Ss / 128, Bb * NHh);
    sgemm<0><<<gV, blk>>>(Sc, Vm, Att, Ss, HDim, Ss,
                          (long)Ss * Ss, (long)Ss * HDim, (long)Ss * HDim);

    // 6) Final: Y = Att @ W_o   [4096x2048]
    sgemm<0><<<gP, blk>>>(Att, Wo, Y, BS, Hh, Hh, 0, 0, 0);
}

// round 2
// speedup vs baseline: 2.2854x; 2.2854x over previous
#include <cuda_runtime.h>
#include <cuda_bf16.h>
#include <cstdint>

#define Ss   2048
#define Hh   2048
#define BS   4096
#define NZ   32          // B * NUM_HEADS
#define HDim 128

typedef __nv_bfloat16 bf16;

// ---------------- fp32 scratch ----------------
__device__ float g_WcT[4194304];      // current combined-weight^T (reused q/k/v)
__device__ float g_Qm[8388608];
__device__ float g_Km[8388608];
__device__ float g_Vm[8388608];
__device__ float g_Sc[134217728];     // scores (fp32)
__device__ float g_Att[8388608];

// ---------------- bf16 hi/lo scratch ----------------
__device__ bf16 g_tAh[4194304], g_tAl[4194304];   // W?m^T / Wo^T (sequential reuse)
__device__ bf16 g_tBh[4194304], g_tBl[4194304];   // Wq/Wk/Wv splits (sequential reuse)
__device__ bf16 g_WcTh[4194304], g_WcTl[4194304]; // combined weight^T split (sequential reuse)
__device__ bf16 g_Xh[8388608],  g_Xl[8388608];
__device__ bf16 g_Qmh[8388608], g_Qml[8388608];
__device__ bf16 g_Kmh[8388608], g_Kml[8388608];
__device__ bf16 g_Vth[8388608], g_Vtl[8388608];   // per-head V^T: [32][128][2048]
__device__ bf16 g_Ph[134217728], g_Pl[134217728]; // softmax probs split
__device__ bf16 g_Atth[8388608], g_Attl[8388608];

// ---------------------------------------------------------------------------
// helpers
// ---------------------------------------------------------------------------
__device__ __forceinline__ void ldsm4(uint32_t a, uint32_t &r0, uint32_t &r1,
                                      uint32_t &r2, uint32_t &r3) {
    asm volatile("ldmatrix.sync.aligned.m8n8.x4.shared.b16 {%0,%1,%2,%3}, [%4];"
                 : "=r"(r0), "=r"(r1), "=r"(r2), "=r"(r3) : "r"(a));
}
__device__ __forceinline__ void mma16816(float c[4], uint32_t a0, uint32_t a1,
                                         uint32_t a2, uint32_t a3,
                                         uint32_t b0, uint32_t b1) {
    asm volatile("mma.sync.aligned.m16n8k16.row.col.f32.bf16.bf16.f32 "
                 "{%0,%1,%2,%3}, {%4,%5,%6,%7}, {%8,%9}, {%0,%1,%2,%3};"
                 : "+f"(c[0]), "+f"(c[1]), "+f"(c[2]), "+f"(c[3])
                 : "r"(a0), "r"(a1), "r"(a2), "r"(a3), "r"(b0), "r"(b1));
}
__device__ __forceinline__ void cpa16(uint32_t s, const void* g) {
    asm volatile("cp.async.cg.shared.global [%0], [%1], 16;" :: "r"(s), "l"(g));
}
__device__ __forceinline__ void split2(float x, bf16 &h, bf16 &l) {
    h = __float2bfloat16(x);
    l = __float2bfloat16(x - __bfloat162float(h));
}

// ---------------------------------------------------------------------------
// bf16x3 NT GEMM: C[M][N] = (Ah+Al)[M][K] @ (Bh+Bl)[N][K]^T (fp32 accum)
// 128x128 tile, BK=32, 256 threads (8 warps, 2x4), mma m16n8k16.
// Dynamic smem 64KB: 2 stages x {Ah,Al,Bh,Bl} x 8KB, XOR-swizzled.
// ---------------------------------------------------------------------------
__global__ void __launch_bounds__(256)
mma_nt(const bf16* __restrict__ Ah, const bf16* __restrict__ Al,
       const bf16* __restrict__ Bh, const bf16* __restrict__ Bl,
       float* __restrict__ C,
       int M, int N, int K, int lda, int ldb, int ldc,
       long sA, long sB, long sC)
{
    extern __shared__ char smem[];
    const uint32_t sbase = (uint32_t)__cvta_generic_to_shared(smem);

    const int z = blockIdx.z;
    Ah += (long)z * sA;  Al += (long)z * sA;
    Bh += (long)z * sB;  Bl += (long)z * sB;
    C  += (long)z * sC;

    const int m0 = blockIdx.y * 128;
    const int n0 = blockIdx.x * 128;
    const int tid  = threadIdx.x;
    const int lane = tid & 31;
    const int w    = tid >> 5;
    const int wm   = (w >> 2) * 64;   // warp m offset (0/64)
    const int wn   = (w & 3) * 32;    // warp n offset (0/32/64/96)

    // ldmatrix lane address components
    const int la15 = lane & 15;
    const int lac  = lane >> 4;               // A chunk +0/+1
    const int lb   = ((lane >> 4) << 3) + (lane & 7);  // B row-within-pair
    const int lbg  = (lane >> 3) & 1;         // B chunk +0/+1

    int offA[4], swA[4];
#pragma unroll
    for (int i = 0; i < 4; i++) {
        int r = wm + i * 16 + la15;
        offA[i] = r * 64;  swA[i] = (r >> 1) & 3;
    }
    int offB[2], swB[2];
#pragma unroll
    for (int p = 0; p < 2; p++) {
        int r = wn + p * 16 + lb;
        offB[p] = r * 64;  swB[p] = (r >> 1) & 3;
    }

    float acc[4][4][4];
#pragma unroll
    for (int i = 0; i < 4; i++)
#pragma unroll
        for (int j = 0; j < 4; j++)
#pragma unroll
            for (int r = 0; r < 4; r++) acc[i][j][r] = 0.0f;

    auto load_stage = [&](int k0, int st) {
        const uint32_t sb = sbase + st * 32768;
#pragma unroll
        for (int qq = 0; qq < 2; qq++) {
            const int q = tid * 2 + qq;      // 0..511
            const int row = q >> 2, c = q & 3;
            const uint32_t sw = row * 64 + ((c ^ ((row >> 1) & 3)) << 4);
            const long ao = (long)(m0 + row) * lda + k0 + c * 8;
            const long bo = (long)(n0 + row) * ldb + k0 + c * 8;
            cpa16(sb + sw,         Ah + ao);
            cpa16(sb + 8192 + sw,  Al + ao);
            cpa16(sb + 16384 + sw, Bh + bo);
            cpa16(sb + 24576 + sw, Bl + bo);
        }
        asm volatile("cp.async.commit_group;" ::: "memory");
    };

    load_stage(0, 0);
    const int T = K >> 5;

    for (int t = 0; t < T; t++) {
        asm volatile("cp.async.wait_group 0;" ::: "memory");
        __syncthreads();
        if (t + 1 < T) load_stage((t + 1) * 32, (t + 1) & 1);

        const uint32_t sb = sbase + (t & 1) * 32768;
#pragma unroll
        for (int kk = 0; kk < 2; kk++) {          // k offset = kk*16
            uint32_t bh[8], bl[8], a[16];
#pragma unroll
            for (int p = 0; p < 2; p++) {
                const uint32_t ca = (uint32_t)(((kk * 2) + lbg) ^ swB[p]) << 4;
                ldsm4(sb + 16384 + offB[p] + ca, bh[p*4], bh[p*4+1], bh[p*4+2], bh[p*4+3]);
                ldsm4(sb + 24576 + offB[p] + ca, bl[p*4], bl[p*4+1], bl[p*4+2], bl[p*4+3]);
            }
#pragma unroll
            for (int i = 0; i < 4; i++) {
                const uint32_t ca = (uint32_t)(((kk * 2) + lac) ^ swA[i]) << 4;
                ldsm4(sb + offA[i] + ca, a[i*4], a[i*4+1], a[i*4+2], a[i*4+3]);
            }
#pragma unroll
            for (int i = 0; i < 4; i++)
#pragma unroll
                for (int j = 0; j < 4; j++) {
                    mma16816(acc[i][j], a[i*4], a[i*4+1], a[i*4+2], a[i*4+3], bh[2*j], bh[2*j+1]);
                    mma16816(acc[i][j], a[i*4], a[i*4+1], a[i*4+2], a[i*4+3], bl[2*j], bl[2*j+1]);
                }
#pragma unroll
            for (int i = 0; i < 4; i++) {
                const uint32_t ca = (uint32_t)(((kk * 2) + lac) ^ swA[i]) << 4;
                ldsm4(sb + 8192 + offA[i] + ca, a[i*4], a[i*4+1], a[i*4+2], a[i*4+3]);
            }
#pragma unroll
            for (int i = 0; i < 4; i++)
#pragma unroll
                for (int j = 0; j < 4; j++)
                    mma16816(acc[i][j], a[i*4], a[i*4+1], a[i*4+2], a[i*4+3], bh[2*j], bh[2*j+1]);
        }
    }

    // epilogue: fp32 C
    const int rr = lane >> 2, cc = (lane & 3) * 2;
#pragma unroll
    for (int i = 0; i < 4; i++) {
        const int row = m0 + wm + i * 16 + rr;
#pragma unroll
        for (int j = 0; j < 4; j++) {
            const int col = n0 + wn + j * 8 + cc;
            *(float2*)&C[(long)row * ldc + col]       = make_float2(acc[i][j][0], acc[i][j][1]);
            *(float2*)&C[(long)(row + 8) * ldc + col] = make_float2(acc[i][j][2], acc[i][j][3]);
        }
    }
}

// ---------------------------------------------------------------------------
// split fp32 -> (hi, lo) bf16, same layout
// ---------------------------------------------------------------------------
__global__ void __launch_bounds__(256)
split_plain(const float* __restrict__ in, bf16* __restrict__ oh,
            bf16* __restrict__ ol, long n4)
{
    long i = (long)blockIdx.x * blockDim.x + threadIdx.x;
    const long stride = (long)gridDim.x * blockDim.x;
    for (; i < n4; i += stride) {
        const float4 v = ((const float4*)in)[i];
        bf16 h0, h1, h2, h3, l0, l1, l2, l3;
        split2(v.x, h0, l0); split2(v.y, h1, l1);
        split2(v.z, h2, l2); split2(v.w, h3, l3);
        ((__nv_bfloat162*)oh)[i*2]   = __halves2bfloat162(h0, h1);
        ((__nv_bfloat162*)oh)[i*2+1] = __halves2bfloat162(h2, h3);
        ((__nv_bfloat162*)ol)[i*2]   = __halves2bfloat162(l0, l1);
        ((__nv_bfloat162*)ol)[i*2+1] = __halves2bfloat162(l2, l3);
    }
}

// ---------------------------------------------------------------------------
// split fp32 [R][C] -> transposed (hi, lo) bf16 [C][R]; batched by blockIdx.z
// ---------------------------------------------------------------------------
__global__ void __launch_bounds__(256)
split_tr(const float* __restrict__ in, bf16* __restrict__ oh,
         bf16* __restrict__ ol, int R, int C)
{
    __shared__ float t[32][33];
    const long zo = (long)blockIdx.z * R * C;
    in += zo; oh += zo; ol += zo;
    const int c0 = blockIdx.x * 32, r0 = blockIdx.y * 32;
    const int tx = threadIdx.x, ty = threadIdx.y;
#pragma unroll
    for (int i = 0; i < 4; i++)
        t[ty + i * 8][tx] = in[(long)(r0 + ty + i * 8) * C + c0 + tx];
    __syncthreads();
#pragma unroll
    for (int i = 0; i < 4; i++) {
        const float v = t[tx][ty + i * 8];
        bf16 h, l; split2(v, h, l);
        const long o = (long)(c0 + ty + i * 8) * R + r0 + tx;
        oh[o] = h; ol[o] = l;
    }
}

// ---------------------------------------------------------------------------
// masked softmax over score rows; writes split bf16 probabilities
// ---------------------------------------------------------------------------
__global__ void __launch_bounds__(256)
masked_softmax_split(const float* __restrict__ scores, const int* __restrict__ mask,
                     bf16* __restrict__ ph, bf16* __restrict__ pl)
{
    const long r = blockIdx.x;
    const int  q = (int)(r & (Ss - 1));
    const int  z = (int)(r >> 11);
    const int  b = z >> 4;
    const float* row  = scores + r * (long)Ss;
    const int*   mrow = mask + b * Ss;
    const int    mq   = mrow[q];
    const int    tid  = threadIdx.x;

    __shared__ float red_m[8];
    __shared__ float red_s[8];

    float v[8];
    float mx = -3.0e38f;
#pragma unroll
    for (int i = 0; i < 8; i++) {
        const int k = tid + i * 256;
        float s = row[k];
        if (mq == 0 || mrow[k] == 0) s = -1000000.0f;
        v[i] = s;
        mx = fmaxf(mx, s);
    }
#pragma unroll
    for (int o = 16; o > 0; o >>= 1)
        mx = fmaxf(mx, __shfl_xor_sync(0xffffffffu, mx, o));
    if ((tid & 31) == 0) red_m[tid >> 5] = mx;
    __syncthreads();
    mx = red_m[0];
#pragma unroll
    for (int i = 1; i < 8; i++) mx = fmaxf(mx, red_m[i]);

    float sum = 0.0f;
#pragma unroll
    for (int i = 0; i < 8; i++) {
        v[i] = __expf(v[i] - mx);
        sum += v[i];
    }
#pragma unroll
    for (int o = 16; o > 0; o >>= 1)
        sum += __shfl_xor_sync(0xffffffffu, sum, o);
    if ((tid & 31) == 0) red_s[tid >> 5] = sum;
    __syncthreads();
    float tot = red_s[0];
#pragma unroll
    for (int i = 1; i < 8; i++) tot += red_s[i];

    const float inv = 1.0f / tot;
#pragma unroll
    for (int i = 0; i < 8; i++) {
        const float p = v[i] * inv;
        bf16 h, l; split2(p, h, l);
        const long o = r * (long)Ss + tid + i * 256;
        ph[o] = h; pl[o] = l;
    }
}

// ---------------------------------------------------------------------------
extern "C" void kernel_launch(void* const* d_in, const int* in_sizes, int n_in,
                              void* d_out, int out_size)
{
    (void)in_sizes; (void)n_in; (void)out_size;
    const float* X   = (const float*)d_in[0];
    const int*   msk = (const int*)  d_in[1];
    const float* Wq  = (const float*)d_in[2];
    const float* Wk  = (const float*)d_in[3];
    const float* Wv  = (const float*)d_in[4];
    const float* Wqm = (const float*)d_in[5];
    const float* Wkm = (const float*)d_in[6];
    const float* Wvm = (const float*)d_in[7];
    const float* Wo  = (const float*)d_in[8];
    float* Y = (float*)d_out;

    float *WcT, *Qm, *Km, *Vm, *Sc, *Att;
    bf16 *tAh, *tAl, *tBh, *tBl, *WcTh, *WcTl, *Xh, *Xl;
    bf16 *Qmh, *Qml, *Kmh, *Kml, *Vth, *Vtl, *Ph, *Pl, *Atth, *Attl;
    cudaGetSymbolAddress((void**)&WcT,  g_WcT);
    cudaGetSymbolAddress((void**)&Qm,   g_Qm);
    cudaGetSymbolAddress((void**)&Km,   g_Km);
    cudaGetSymbolAddress((void**)&Vm,   g_Vm);
    cudaGetSymbolAddress((void**)&Sc,   g_Sc);
    cudaGetSymbolAddress((void**)&Att,  g_Att);
    cudaGetSymbolAddress((void**)&tAh,  g_tAh);  cudaGetSymbolAddress((void**)&tAl,  g_tAl);
    cudaGetSymbolAddress((void**)&tBh,  g_tBh);  cudaGetSymbolAddress((void**)&tBl,  g_tBl);
    cudaGetSymbolAddress((void**)&WcTh, g_WcTh); cudaGetSymbolAddress((void**)&WcTl, g_WcTl);
    cudaGetSymbolAddress((void**)&Xh,   g_Xh);   cudaGetSymbolAddress((void**)&Xl,   g_Xl);
    cudaGetSymbolAddress((void**)&Qmh,  g_Qmh);  cudaGetSymbolAddress((void**)&Qml,  g_Qml);
    cudaGetSymbolAddress((void**)&Kmh,  g_Kmh);  cudaGetSymbolAddress((void**)&Kml,  g_Kml);
    cudaGetSymbolAddress((void**)&Vth,  g_Vth);  cudaGetSymbolAddress((void**)&Vtl,  g_Vtl);
    cudaGetSymbolAddress((void**)&Ph,   g_Ph);   cudaGetSymbolAddress((void**)&Pl,   g_Pl);
    cudaGetSymbolAddress((void**)&Atth, g_Atth); cudaGetSymbolAddress((void**)&Attl, g_Attl);

    cudaFuncSetAttribute(mma_nt, cudaFuncAttributeMaxDynamicSharedMemorySize, 65536);

    const dim3 b256(256);
    const dim3 bTr(32, 8);
    const dim3 gTrW(Hh / 32, Hh / 32, 1);       // 2048x2048 transpose
    const dim3 gW(16, 16, 1);                    // 2048x2048 GEMM
    const dim3 gP(16, 32, 1);                    // 4096x2048 GEMM
    const unsigned SPW = 4096;                   // split blocks for 4M elems
    const unsigned SPX = 8192;                   // split blocks for 8M elems

    // split X once
    split_plain<<<SPX, b256>>>(X, Xh, Xl, 8388608 / 4);

    const float* Wt[3]  = {Wq, Wk, Wv};
    const float* Wmt[3] = {Wqm, Wkm, Wvm};
    float* Pout[3]      = {Qm, Km, Vm};
    for (int s = 0; s < 3; s++) {
        // WcT = Wm^T @ W^T  via NT: A = Wm^T (split_tr), B = W (split_plain)
        split_plain<<<SPW, b256>>>(Wt[s], tBh, tBl, 4194304 / 4);
        split_tr<<<gTrW, bTr>>>(Wmt[s], tAh, tAl, Hh, Hh);
        mma_nt<<<gW, b256, 65536>>>(tAh, tAl, tBh, tBl, WcT,
                                    Hh, Hh, Hh, Hh, Hh, Hh, 0, 0, 0);
        split_plain<<<SPW, b256>>>(WcT, WcTh, WcTl, 4194304 / 4);
        // P = X @ Wc  via NT: B = WcT
        mma_nt<<<gP, b256, 65536>>>(Xh, Xl, WcTh, WcTl, Pout[s],
                                    BS, Hh, Hh, Hh, Hh, Hh, 0, 0, 0);
    }

    // splits for attention operands (head blocks are contiguous 2048x128 rows)
    split_plain<<<SPX, b256>>>(Qm, Qmh, Qml, 8388608 / 4);
    split_plain<<<SPX, b256>>>(Km, Kmh, Kml, 8388608 / 4);
    split_tr<<<dim3(HDim / 32, Ss / 32, NZ), bTr>>>(Vm, Vth, Vtl, Ss, HDim);

    // scores: Sc_z = Qh_z @ Kh_z^T   (A,B viewed as [NZ*2048][128])
    mma_nt<<<dim3(16, 16, NZ), b256, 65536>>>(
        Qmh, Qml, Kmh, Kml, Sc,
        Ss, Ss, HDim, HDim, HDim, Ss,
        (long)Ss * HDim, (long)Ss * HDim, (long)Ss * Ss);

    // masked softmax + split
    masked_softmax_split<<<(unsigned)(NZ * Ss), b256>>>(Sc, msk, Ph, Pl);

    // PV: Att_z = P_z @ V_z  via NT with B = V_z^T [128][2048]
    mma_nt<<<dim3(1, 16, NZ), b256, 65536>>>(
        Ph, Pl, Vth, Vtl, Att,
        Ss, HDim, Ss, Ss, Ss, HDim,
        (long)Ss * Ss, (long)HDim * Ss, (long)Ss * HDim);

    // final: Y = Att @ Wo  via NT with B = Wo^T (Att flat == token-major)
    split_plain<<<SPX, b256>>>(Att, Atth, Attl, 8388608 / 4);
    split_tr<<<gTrW, bTr>>>(Wo, tAh, tAl, Hh, Hh);
    mma_nt<<<gP, b256, 65536>>>(Atth, Attl, tAh, tAl, Y,
                                BS, Hh, Hh, Hh, Hh, Hh, 0, 0, 0);
}

// round 4
// speedup vs baseline: 2.6071x; 1.1408x over previous
#include <cuda_runtime.h>
#include <cuda_bf16.h>
#include <cstdint>

#define Ss   2048
#define Hh   2048
#define BS   4096
#define NZ   32          // B * NUM_HEADS
#define HDim 128

typedef __nv_bfloat16 bf16;

// ---------------- fp32 scratch ----------------
__device__ float g_Vm[8388608];
__device__ float g_Sc[134217728];     // scores (fp32)

// ---------------- bf16 hi/lo scratch ----------------
__device__ bf16 g_tAh[4194304], g_tAl[4194304];   // W?m^T / Wo^T (sequential reuse)
__device__ bf16 g_tBh[4194304], g_tBl[4194304];   // Wq/Wk/Wv splits (sequential reuse)
__device__ bf16 g_WcTh[4194304], g_WcTl[4194304]; // combined weight^T split
__device__ bf16 g_Xh[8388608],  g_Xl[8388608];
__device__ bf16 g_Qmh[8388608], g_Qml[8388608];
__device__ bf16 g_Kmh[8388608], g_Kml[8388608];
__device__ bf16 g_Vth[8388608], g_Vtl[8388608];   // per-head V^T: [32][128][2048]
__device__ bf16 g_Ph[134217728], g_Pl[134217728]; // softmax probs split
__device__ bf16 g_Atth[8388608], g_Attl[8388608];

// ---------------------------------------------------------------------------
// helpers
// ---------------------------------------------------------------------------
__device__ __forceinline__ void ldsm4(uint32_t a, uint32_t &r0, uint32_t &r1,
                                      uint32_t &r2, uint32_t &r3) {
    asm volatile("ldmatrix.sync.aligned.m8n8.x4.shared.b16 {%0,%1,%2,%3}, [%4];"
                 : "=r"(r0), "=r"(r1), "=r"(r2), "=r"(r3) : "r"(a));
}
__device__ __forceinline__ void mma16816(float c[4], uint32_t a0, uint32_t a1,
                                         uint32_t a2, uint32_t a3,
                                         uint32_t b0, uint32_t b1) {
    asm volatile("mma.sync.aligned.m16n8k16.row.col.f32.bf16.bf16.f32 "
                 "{%0,%1,%2,%3}, {%4,%5,%6,%7}, {%8,%9}, {%0,%1,%2,%3};"
                 : "+f"(c[0]), "+f"(c[1]), "+f"(c[2]), "+f"(c[3])
                 : "r"(a0), "r"(a1), "r"(a2), "r"(a3), "r"(b0), "r"(b1));
}
__device__ __forceinline__ void cpa16(uint32_t s, const void* g) {
    asm volatile("cp.async.cg.shared.global [%0], [%1], 16;" :: "r"(s), "l"(g));
}
__device__ __forceinline__ void split2(float x, bf16 &h, bf16 &l) {
    h = __float2bfloat16(x);
    l = __float2bfloat16(x - __bfloat162float(h));
}

// ---------------------------------------------------------------------------
// bf16x3 NT GEMM: C[M][N] = (Ah+Al)[M][K] @ (Bh+Bl)[N][K]^T (fp32 accum)
// 128x128 tile, BK=32, 256 threads (8 warps, 2x4), mma m16n8k16.
// 3-stage cp.async ring: 3 x {Ah,Al,Bh,Bl} x 8KB = 96KB dynamic smem.
// OUT=0: write fp32 C.  OUT=1: write bf16 hi/lo pair (fused split epilogue).
// ---------------------------------------------------------------------------
template <int OUT>
__global__ void __launch_bounds__(256, 2)
mma_nt(const bf16* __restrict__ Ah, const bf16* __restrict__ Al,
       const bf16* __restrict__ Bh, const bf16* __restrict__ Bl,
       float* __restrict__ C, bf16* __restrict__ Ch, bf16* __restrict__ Cl,
       int K, int lda, int ldb, int ldc,
       long sA, long sB, long sC)
{
    extern __shared__ char smem[];
    const uint32_t sbase = (uint32_t)__cvta_generic_to_shared(smem);

    const int z = blockIdx.z;
    Ah += (long)z * sA;  Al += (long)z * sA;
    Bh += (long)z * sB;  Bl += (long)z * sB;

    const int m0 = blockIdx.y * 128;
    const int n0 = blockIdx.x * 128;
    const int tid  = threadIdx.x;
    const int lane = tid & 31;
    const int w    = tid >> 5;
    const int wm   = (w >> 2) * 64;   // warp m offset (0/64)
    const int wn   = (w & 3) * 32;    // warp n offset (0/32/64/96)

    const int la15 = lane & 15;
    const int lac  = lane >> 4;
    const int lb   = ((lane >> 4) << 3) + (lane & 7);
    const int lbg  = (lane >> 3) & 1;

    int offA[4], swA[4];
#pragma unroll
    for (int i = 0; i < 4; i++) {
        int r = wm + i * 16 + la15;
        offA[i] = r * 64;  swA[i] = (r >> 1) & 3;
    }
    int offB[2], swB[2];
#pragma unroll
    for (int p = 0; p < 2; p++) {
        int r = wn + p * 16 + lb;
        offB[p] = r * 64;  swB[p] = (r >> 1) & 3;
    }

    float acc[4][4][4];
#pragma unroll
    for (int i = 0; i < 4; i++)
#pragma unroll
        for (int j = 0; j < 4; j++)
#pragma unroll
            for (int r = 0; r < 4; r++) acc[i][j][r] = 0.0f;

    auto load_stage = [&](int t, int st) {
        const uint32_t sb = sbase + st * 32768;
        const int k0 = t * 32;
#pragma unroll
        for (int qq = 0; qq < 2; qq++) {
            const int q = tid * 2 + qq;      // 0..511
            const int row = q >> 2, c = q & 3;
            const uint32_t sw = row * 64 + ((c ^ ((row >> 1) & 3)) << 4);
            const long ao = (long)(m0 + row) * lda + k0 + c * 8;
            const long bo = (long)(n0 + row) * ldb + k0 + c * 8;
            cpa16(sb + sw,         Ah + ao);
            cpa16(sb + 8192 + sw,  Al + ao);
            cpa16(sb + 16384 + sw, Bh + bo);
            cpa16(sb + 24576 + sw, Bl + bo);
        }
        asm volatile("cp.async.commit_group;" ::: "memory");
    };

    const int T = K >> 5;
    load_stage(0, 0);
    load_stage(1, 1);

    int st = 0;
    for (int t = 0; t < T; t++) {
        if (t < T - 1) asm volatile("cp.async.wait_group 1;" ::: "memory");
        else           asm volatile("cp.async.wait_group 0;" ::: "memory");
        __syncthreads();
        if (t + 2 < T) {
            int ns = st + 2; if (ns >= 3) ns -= 3;
            load_stage(t + 2, ns);
        }

        const uint32_t sb = sbase + st * 32768;
#pragma unroll
        for (int kk = 0; kk < 2; kk++) {          // k offset = kk*16
            uint32_t bh[8], bl[8], a[16];
#pragma unroll
            for (int p = 0; p < 2; p++) {
                const uint32_t ca = (uint32_t)(((kk * 2) + lbg) ^ swB[p]) << 4;
                ldsm4(sb + 16384 + offB[p] + ca, bh[p*4], bh[p*4+1], bh[p*4+2], bh[p*4+3]);
                ldsm4(sb + 24576 + offB[p] + ca, bl[p*4], bl[p*4+1], bl[p*4+2], bl[p*4+3]);
            }
#pragma unroll
            for (int i = 0; i < 4; i++) {
                const uint32_t ca = (uint32_t)(((kk * 2) + lac) ^ swA[i]) << 4;
                ldsm4(sb + offA[i] + ca, a[i*4], a[i*4+1], a[i*4+2], a[i*4+3]);
            }
#pragma unroll
            for (int i = 0; i < 4; i++)
#pragma unroll
                for (int j = 0; j < 4; j++) {
                    mma16816(acc[i][j], a[i*4], a[i*4+1], a[i*4+2], a[i*4+3], bh[2*j], bh[2*j+1]);
                    mma16816(acc[i][j], a[i*4], a[i*4+1], a[i*4+2], a[i*4+3], bl[2*j], bl[2*j+1]);
                }
#pragma unroll
            for (int i = 0; i < 4; i++) {
                const uint32_t ca = (uint32_t)(((kk * 2) + lac) ^ swA[i]) << 4;
                ldsm4(sb + 8192 + offA[i] + ca, a[i*4], a[i*4+1], a[i*4+2], a[i*4+3]);
            }
#pragma unroll
            for (int i = 0; i < 4; i++)
#pragma unroll
                for (int j = 0; j < 4; j++)
                    mma16816(acc[i][j], a[i*4], a[i*4+1], a[i*4+2], a[i*4+3], bh[2*j], bh[2*j+1]);
        }
        if (++st == 3) st = 0;
    }

    // epilogue
    const int rr = lane >> 2, cc = (lane & 3) * 2;
#pragma unroll
    for (int i = 0; i < 4; i++) {
        const int row = m0 + wm + i * 16 + rr;
#pragma unroll
        for (int j = 0; j < 4; j++) {
            const int col = n0 + wn + j * 8 + cc;
            if (OUT == 0) {
                float* Cz = C + (long)z * sC;
                *(float2*)&Cz[(long)row * ldc + col]       = make_float2(acc[i][j][0], acc[i][j][1]);
                *(float2*)&Cz[(long)(row + 8) * ldc + col] = make_float2(acc[i][j][2], acc[i][j][3]);
            } else {
                bf16* Chz = Ch + (long)z * sC;
                bf16* Clz = Cl + (long)z * sC;
                bf16 h0, h1, l0, l1;
                split2(acc[i][j][0], h0, l0); split2(acc[i][j][1], h1, l1);
                *(__nv_bfloat162*)&Chz[(long)row * ldc + col] = __halves2bfloat162(h0, h1);
                *(__nv_bfloat162*)&Clz[(long)row * ldc + col] = __halves2bfloat162(l0, l1);
                split2(acc[i][j][2], h0, l0); split2(acc[i][j][3], h1, l1);
                *(__nv_bfloat162*)&Chz[(long)(row + 8) * ldc + col] = __halves2bfloat162(h0, h1);
                *(__nv_bfloat162*)&Clz[(long)(row + 8) * ldc + col] = __halves2bfloat162(l0, l1);
            }
        }
    }
}

// ---------------------------------------------------------------------------
// split fp32 -> (hi, lo) bf16, same layout
// ---------------------------------------------------------------------------
__global__ void __launch_bounds__(256)
split_plain(const float* __restrict__ in, bf16* __restrict__ oh,
            bf16* __restrict__ ol, long n4)
{
    long i = (long)blockIdx.x * blockDim.x + threadIdx.x;
    const long stride = (long)gridDim.x * blockDim.x;
    for (; i < n4; i += stride) {
        const float4 v = ((const float4*)in)[i];
        bf16 h0, h1, h2, h3, l0, l1, l2, l3;
        split2(v.x, h0, l0); split2(v.y, h1, l1);
        split2(v.z, h2, l2); split2(v.w, h3, l3);
        ((__nv_bfloat162*)oh)[i*2]   = __halves2bfloat162(h0, h1);
        ((__nv_bfloat162*)oh)[i*2+1] = __halves2bfloat162(h2, h3);
        ((__nv_bfloat162*)ol)[i*2]   = __halves2bfloat162(l0, l1);
        ((__nv_bfloat162*)ol)[i*2+1] = __halves2bfloat162(l2, l3);
    }
}

// ---------------------------------------------------------------------------
// split fp32 [R][C] -> transposed (hi, lo) bf16 [C][R]; batched by blockIdx.z
// ---------------------------------------------------------------------------
__global__ void __launch_bounds__(256)
split_tr(const float* __restrict__ in, bf16* __restrict__ oh,
         bf16* __restrict__ ol, int R, int C)
{
    __shared__ float t[32][33];
    const long zo = (long)blockIdx.z * R * C;
    in += zo; oh += zo; ol += zo;
    const int c0 = blockIdx.x * 32, r0 = blockIdx.y * 32;
    const int tx = threadIdx.x, ty = threadIdx.y;
#pragma unroll
    for (int i = 0; i < 4; i++)
        t[ty + i * 8][tx] = in[(long)(r0 + ty + i * 8) * C + c0 + tx];
    __syncthreads();
#pragma unroll
    for (int i = 0; i < 4; i++) {
        const float v = t[tx][ty + i * 8];
        bf16 h, l; split2(v, h, l);
        const long o = (long)(c0 + ty + i * 8) * R + r0 + tx;
        oh[o] = h; ol[o] = l;
    }
}

// ---------------------------------------------------------------------------
// masked softmax over score rows; writes split bf16 probabilities
// ---------------------------------------------------------------------------
__global__ void __launch_bounds__(256)
masked_softmax_split(const float* __restrict__ scores, const int* __restrict__ mask,
                     bf16* __restrict__ ph, bf16* __restrict__ pl)
{
    const long r = blockIdx.x;
    const int  q = (int)(r & (Ss - 1));
    const int  z = (int)(r >> 11);
    const int  b = z >> 4;
    const float* row  = scores + r * (long)Ss;
    const int*   mrow = mask + b * Ss;
    const int    mq   = mrow[q];
    const int    tid  = threadIdx.x;

    __shared__ float red_m[8];
    __shared__ float red_s[8];

    float v[8];
    float mx = -3.0e38f;
#pragma unroll
    for (int i = 0; i < 8; i++) {
        const int k = tid + i * 256;
        float s = row[k];
        if (mq == 0 || mrow[k] == 0) s = -1000000.0f;
        v[i] = s;
        mx = fmaxf(mx, s);
    }
#pragma unroll
    for (int o = 16; o > 0; o >>= 1)
        mx = fmaxf(mx, __shfl_xor_sync(0xffffffffu, mx, o));
    if ((tid & 31) == 0) red_m[tid >> 5] = mx;
    __syncthreads();
    mx = red_m[0];
#pragma unroll
    for (int i = 1; i < 8; i++) mx = fmaxf(mx, red_m[i]);

    float sum = 0.0f;
#pragma unroll
    for (int i = 0; i < 8; i++) {
        v[i] = __expf(v[i] - mx);
        sum += v[i];
    }
#pragma unroll
    for (int o = 16; o > 0; o >>= 1)
        sum += __shfl_xor_sync(0xffffffffu, sum, o);
    if ((tid & 31) == 0) red_s[tid >> 5] = sum;
    __syncthreads();
    float tot = red_s[0];
#pragma unroll
    for (int i = 1; i < 8; i++) tot += red_s[i];

    const float inv = 1.0f / tot;
#pragma unroll
    for (int i = 0; i < 8; i++) {
        const float p = v[i] * inv;
        bf16 h, l; split2(p, h, l);
        const long o = r * (long)Ss + tid + i * 256;
        ph[o] = h; pl[o] = l;
    }
}

// ---------------------------------------------------------------------------
extern "C" void kernel_launch(void* const* d_in, const int* in_sizes, int n_in,
                              void* d_out, int out_size)
{
    (void)in_sizes; (void)n_in; (void)out_size;
    const float* X   = (const float*)d_in[0];
    const int*   msk = (const int*)  d_in[1];
    const float* Wq  = (const float*)d_in[2];
    const float* Wk  = (const float*)d_in[3];
    const float* Wv  = (const float*)d_in[4];
    const float* Wqm = (const float*)d_in[5];
    const float* Wkm = (const float*)d_in[6];
    const float* Wvm = (const float*)d_in[7];
    const float* Wo  = (const float*)d_in[8];
    float* Y = (float*)d_out;

    float *Vm, *Sc;
    bf16 *tAh, *tAl, *tBh, *tBl, *WcTh, *WcTl, *Xh, *Xl;
    bf16 *Qmh, *Qml, *Kmh, *Kml, *Vth, *Vtl, *Ph, *Pl, *Atth, *Attl;
    cudaGetSymbolAddress((void**)&Vm,   g_Vm);
    cudaGetSymbolAddress((void**)&Sc,   g_Sc);
    cudaGetSymbolAddress((void**)&tAh,  g_tAh);  cudaGetSymbolAddress((void**)&tAl,  g_tAl);
    cudaGetSymbolAddress((void**)&tBh,  g_tBh);  cudaGetSymbolAddress((void**)&tBl,  g_tBl);
    cudaGetSymbolAddress((void**)&WcTh, g_WcTh); cudaGetSymbolAddress((void**)&WcTl, g_WcTl);
    cudaGetSymbolAddress((void**)&Xh,   g_Xh);   cudaGetSymbolAddress((void**)&Xl,   g_Xl);
    cudaGetSymbolAddress((void**)&Qmh,  g_Qmh);  cudaGetSymbolAddress((void**)&Qml,  g_Qml);
    cudaGetSymbolAddress((void**)&Kmh,  g_Kmh);  cudaGetSymbolAddress((void**)&Kml,  g_Kml);
    cudaGetSymbolAddress((void**)&Vth,  g_Vth);  cudaGetSymbolAddress((void**)&Vtl,  g_Vtl);
    cudaGetSymbolAddress((void**)&Ph,   g_Ph);   cudaGetSymbolAddress((void**)&Pl,   g_Pl);
    cudaGetSymbolAddress((void**)&Atth, g_Atth); cudaGetSymbolAddress((void**)&Attl, g_Attl);

    const unsigned SMB = 98304;   // 3 stages * 32KB
    cudaFuncSetAttribute(mma_nt<0>, cudaFuncAttributeMaxDynamicSharedMemorySize, SMB);
    cudaFuncSetAttribute(mma_nt<1>, cudaFuncAttributeMaxDynamicSharedMemorySize, SMB);

    const dim3 b256(256);
    const dim3 bTr(32, 8);
    const dim3 gTrW(Hh / 32, Hh / 32, 1);
    const dim3 gW(16, 16, 1);
    const dim3 gP(16, 32, 1);
    const unsigned SPW = 4096;
    const unsigned SPX = 8192;

    // split X once
    split_plain<<<SPX, b256>>>(X, Xh, Xl, 8388608 / 4);

    const float* Wt[3]  = {Wq, Wk, Wv};
    const float* Wmt[3] = {Wqm, Wkm, Wvm};
    for (int s = 0; s < 3; s++) {
        // WcT = Wm^T @ W^T via NT, split-out epilogue
        split_plain<<<SPW, b256>>>(Wt[s], tBh, tBl, 4194304 / 4);
        split_tr<<<gTrW, bTr>>>(Wmt[s], tAh, tAl, Hh, Hh);
        mma_nt<1><<<gW, b256, SMB>>>(tAh, tAl, tBh, tBl, nullptr, WcTh, WcTl,
                                     Hh, Hh, Hh, Hh, 0, 0, 0);
        // P = X @ Wc via NT (B = WcT); Q/K -> split out, V -> fp32 (needs transpose)
        if (s == 0)
            mma_nt<1><<<gP, b256, SMB>>>(Xh, Xl, WcTh, WcTl, nullptr, Qmh, Qml,
                                         Hh, Hh, Hh, Hh, 0, 0, 0);
        else if (s == 1)
            mma_nt<1><<<gP, b256, SMB>>>(Xh, Xl, WcTh, WcTl, nullptr, Kmh, Kml,
                                         Hh, Hh, Hh, Hh, 0, 0, 0);
        else
            mma_nt<0><<<gP, b256, SMB>>>(Xh, Xl, WcTh, WcTl, Vm, nullptr, nullptr,
                                         Hh, Hh, Hh, Hh, 0, 0, 0);
    }

    // per-head V^T (hi/lo)
    split_tr<<<dim3(HDim / 32, Ss / 32, NZ), bTr>>>(Vm, Vth, Vtl, Ss, HDim);

    // scores: Sc_z = Qh_z @ Kh_z^T
    mma_nt<0><<<dim3(16, 16, NZ), b256, SMB>>>(
        Qmh, Qml, Kmh, Kml, Sc, nullptr, nullptr,
        HDim, HDim, HDim, Ss,
        (long)Ss * HDim, (long)Ss * HDim, (long)Ss * Ss);

    // masked softmax + split
    masked_softmax_split<<<(unsigned)(NZ * Ss), b256>>>(Sc, msk, Ph, Pl);

    // PV: Att_z = P_z @ V_z via NT with B = V_z^T, split-out epilogue
    mma_nt<1><<<dim3(1, 16, NZ), b256, SMB>>>(
        Ph, Pl, Vth, Vtl, nullptr, Atth, Attl,
        Ss, Ss, Ss, HDim,
        (long)Ss * Ss, (long)HDim * Ss, (long)Ss * HDim);

    // final: Y = Att @ Wo via NT with B = Wo^T
    split_tr<<<gTrW, bTr>>>(Wo, tAh, tAl, Hh, Hh);
    mma_nt<0><<<gP, b256, SMB>>>(Atth, Attl, tAh, tAl, Y, nullptr, nullptr,
                                 Hh, Hh, Hh, Hh, 0, 0, 0);
}

// round 6
// speedup vs baseline: 3.1521x; 1.2090x over previous
#include <cuda_runtime.h>
#include <cuda_bf16.h>
#include <cstdint>

#define Ss   2048
#define Hh   2048
#define BS   4096
#define NZ   32          // B * NUM_HEADS
#define HDim 128

typedef __nv_bfloat16 bf16;

// ---------------- fp32 scratch ----------------
__device__ float g_Vm[8388608];
__device__ float g_Sc[134217728];     // scores (fp32)

// ---------------- bf16 hi/lo scratch ----------------
__device__ bf16 g_tAh[4194304], g_tAl[4194304];   // W?m^T / Wo^T (sequential reuse)
__device__ bf16 g_tBh[4194304], g_tBl[4194304];   // Wq/Wk/Wv splits (sequential reuse)
__device__ bf16 g_WcTh[4194304], g_WcTl[4194304]; // combined weight^T split
__device__ bf16 g_Xh[8388608],  g_Xl[8388608];
__device__ bf16 g_Qmh[8388608], g_Qml[8388608];
__device__ bf16 g_Kmh[8388608], g_Kml[8388608];
__device__ bf16 g_Vth[8388608], g_Vtl[8388608];   // per-head V^T: [32][128][2048]
__device__ bf16 g_Ph[134217728], g_Pl[134217728]; // softmax probs split
__device__ bf16 g_Atth[8388608], g_Attl[8388608];

// ---------------------------------------------------------------------------
// helpers
// ---------------------------------------------------------------------------
__device__ __forceinline__ void ldsm4(uint32_t a, uint32_t &r0, uint32_t &r1,
                                      uint32_t &r2, uint32_t &r3) {
    asm volatile("ldmatrix.sync.aligned.m8n8.x4.shared.b16 {%0,%1,%2,%3}, [%4];"
                 : "=r"(r0), "=r"(r1), "=r"(r2), "=r"(r3) : "r"(a));
}
__device__ __forceinline__ void mma16816(float c[4], uint32_t a0, uint32_t a1,
                                         uint32_t a2, uint32_t a3,
                                         uint32_t b0, uint32_t b1) {
    asm volatile("mma.sync.aligned.m16n8k16.row.col.f32.bf16.bf16.f32 "
                 "{%0,%1,%2,%3}, {%4,%5,%6,%7}, {%8,%9}, {%0,%1,%2,%3};"
                 : "+f"(c[0]), "+f"(c[1]), "+f"(c[2]), "+f"(c[3])
                 : "r"(a0), "r"(a1), "r"(a2), "r"(a3), "r"(b0), "r"(b1));
}
__device__ __forceinline__ void cpa16(uint32_t s, const void* g) {
    asm volatile("cp.async.cg.shared.global [%0], [%1], 16;" :: "r"(s), "l"(g));
}
__device__ __forceinline__ void split2(float x, bf16 &h, bf16 &l) {
    h = __float2bfloat16(x);
    l = __float2bfloat16(x - __bfloat162float(h));
}

// ---------------------------------------------------------------------------
// bf16x3 NT GEMM: C[M][N] = (Ah+Al)[M][K] @ (Bh+Bl)[N][K]^T (fp32 accum)
// 128x128 CTA tile, BK=32, 128 threads (4 warps, 2x2), warp tile 64x64.
// 3-stage cp.async ring: 3 x {Ah,Al,Bh,Bl} x 8KB = 96KB dynamic smem.
// OUT=0: write fp32 C.  OUT=1: write bf16 hi/lo pair (fused split epilogue).
// ---------------------------------------------------------------------------
template <int OUT>
__global__ void __launch_bounds__(128)
mma_nt(const bf16* __restrict__ Ah, const bf16* __restrict__ Al,
       const bf16* __restrict__ Bh, const bf16* __restrict__ Bl,
       float* __restrict__ C, bf16* __restrict__ Ch, bf16* __restrict__ Cl,
       int K, int lda, int ldb, int ldc,
       long sA, long sB, long sC)
{
    extern __shared__ char smem[];
    const uint32_t sbase = (uint32_t)__cvta_generic_to_shared(smem);

    const int z = blockIdx.z;
    Ah += (long)z * sA;  Al += (long)z * sA;
    Bh += (long)z * sB;  Bl += (long)z * sB;

    const int m0 = blockIdx.y * 128;
    const int n0 = blockIdx.x * 128;
    const int tid  = threadIdx.x;
    const int lane = tid & 31;
    const int w    = tid >> 5;
    const int wm   = (w & 2) * 32;    // warp m offset (0/64)
    const int wn   = (w & 1) * 64;    // warp n offset (0/64)

    const int la15 = lane & 15;
    const int lac  = lane >> 4;
    const int lb   = ((lane >> 4) << 3) + (lane & 7);
    const int lbg  = (lane >> 3) & 1;

    int offA[4], swA[4];
#pragma unroll
    for (int i = 0; i < 4; i++) {
        int r = wm + i * 16 + la15;
        offA[i] = r * 64;  swA[i] = (r >> 1) & 3;
    }
    int offB[4], swB[4];
#pragma unroll
    for (int p = 0; p < 4; p++) {
        int r = wn + p * 16 + lb;
        offB[p] = r * 64;  swB[p] = (r >> 1) & 3;
    }

    float acc[4][8][4];
#pragma unroll
    for (int i = 0; i < 4; i++)
#pragma unroll
        for (int j = 0; j < 8; j++)
#pragma unroll
            for (int r = 0; r < 4; r++) acc[i][j][r] = 0.0f;

    auto load_stage = [&](int t, int st) {
        const uint32_t sb = sbase + st * 32768;
        const int k0 = t * 32;
#pragma unroll
        for (int i = 0; i < 16; i++) {
            const int q = i * 128 + tid;     // 0..2047
            const int tile = q >> 9;         // 0..3
            const int idx = q & 511;
            const int row = idx >> 2, c = idx & 3;
            const uint32_t sw = row * 64 + ((c ^ ((row >> 1) & 3)) << 4);
            const bf16* g;
            if (tile == 0)      g = Ah + (long)(m0 + row) * lda + k0 + c * 8;
            else if (tile == 1) g = Al + (long)(m0 + row) * lda + k0 + c * 8;
            else if (tile == 2) g = Bh + (long)(n0 + row) * ldb + k0 + c * 8;
            else                g = Bl + (long)(n0 + row) * ldb + k0 + c * 8;
            cpa16(sb + tile * 8192 + sw, g);
        }
        asm volatile("cp.async.commit_group;" ::: "memory");
    };

    const int T = K >> 5;
    load_stage(0, 0);
    load_stage(1, 1);

    int st = 0;
    for (int t = 0; t < T; t++) {
        if (t < T - 1) asm volatile("cp.async.wait_group 1;" ::: "memory");
        else           asm volatile("cp.async.wait_group 0;" ::: "memory");
        __syncthreads();
        if (t + 2 < T) {
            int ns = st + 2; if (ns >= 3) ns -= 3;
            load_stage(t + 2, ns);
        }

        const uint32_t sb = sbase + st * 32768;
#pragma unroll
        for (int kk = 0; kk < 2; kk++) {          // k offset = kk*16
            uint32_t bh[16], bl[16], a[16];
#pragma unroll
            for (int p = 0; p < 4; p++) {
                const uint32_t ca = (uint32_t)(((kk * 2) + lbg) ^ swB[p]) << 4;
                ldsm4(sb + 16384 + offB[p] + ca, bh[p*4], bh[p*4+1], bh[p*4+2], bh[p*4+3]);
                ldsm4(sb + 24576 + offB[p] + ca, bl[p*4], bl[p*4+1], bl[p*4+2], bl[p*4+3]);
            }
#pragma unroll
            for (int i = 0; i < 4; i++) {
                const uint32_t ca = (uint32_t)(((kk * 2) + lac) ^ swA[i]) << 4;
                ldsm4(sb + offA[i] + ca, a[i*4], a[i*4+1], a[i*4+2], a[i*4+3]);
            }
#pragma unroll
            for (int i = 0; i < 4; i++)
#pragma unroll
                for (int j = 0; j < 8; j++) {
                    mma16816(acc[i][j], a[i*4], a[i*4+1], a[i*4+2], a[i*4+3], bh[2*j], bh[2*j+1]);
                    mma16816(acc[i][j], a[i*4], a[i*4+1], a[i*4+2], a[i*4+3], bl[2*j], bl[2*j+1]);
                }
#pragma unroll
            for (int i = 0; i < 4; i++) {
                const uint32_t ca = (uint32_t)(((kk * 2) + lac) ^ swA[i]) << 4;
                ldsm4(sb + 8192 + offA[i] + ca, a[i*4], a[i*4+1], a[i*4+2], a[i*4+3]);
            }
#pragma unroll
            for (int i = 0; i < 4; i++)
#pragma unroll
                for (int j = 0; j < 8; j++)
                    mma16816(acc[i][j], a[i*4], a[i*4+1], a[i*4+2], a[i*4+3], bh[2*j], bh[2*j+1]);
        }
        if (++st == 3) st = 0;
    }

    // epilogue
    const int rr = lane >> 2, cc = (lane & 3) * 2;
#pragma unroll
    for (int i = 0; i < 4; i++) {
        const int row = m0 + wm + i * 16 + rr;
#pragma unroll
        for (int j = 0; j < 8; j++) {
            const int col = n0 + wn + j * 8 + cc;
            if (OUT == 0) {
                float* Cz = C + (long)z * sC;
                *(float2*)&Cz[(long)row * ldc + col]       = make_float2(acc[i][j][0], acc[i][j][1]);
                *(float2*)&Cz[(long)(row + 8) * ldc + col] = make_float2(acc[i][j][2], acc[i][j][3]);
            } else {
                bf16* Chz = Ch + (long)z * sC;
                bf16* Clz = Cl + (long)z * sC;
                bf16 h0, h1, l0, l1;
                split2(acc[i][j][0], h0, l0); split2(acc[i][j][1], h1, l1);
                *(__nv_bfloat162*)&Chz[(long)row * ldc + col] = __halves2bfloat162(h0, h1);
                *(__nv_bfloat162*)&Clz[(long)row * ldc + col] = __halves2bfloat162(l0, l1);
                split2(acc[i][j][2], h0, l0); split2(acc[i][j][3], h1, l1);
                *(__nv_bfloat162*)&Chz[(long)(row + 8) * ldc + col] = __halves2bfloat162(h0, h1);
                *(__nv_bfloat162*)&Clz[(long)(row + 8) * ldc + col] = __halves2bfloat162(l0, l1);
            }
        }
    }
}

// ---------------------------------------------------------------------------
// split fp32 -> (hi, lo) bf16, same layout
// ---------------------------------------------------------------------------
__global__ void __launch_bounds__(256)
split_plain(const float* __restrict__ in, bf16* __restrict__ oh,
            bf16* __restrict__ ol, long n4)
{
    long i = (long)blockIdx.x * blockDim.x + threadIdx.x;
    const long stride = (long)gridDim.x * blockDim.x;
    for (; i < n4; i += stride) {
        const float4 v = ((const float4*)in)[i];
        bf16 h0, h1, h2, h3, l0, l1, l2, l3;
        split2(v.x, h0, l0); split2(v.y, h1, l1);
        split2(v.z, h2, l2); split2(v.w, h3, l3);
        ((__nv_bfloat162*)oh)[i*2]   = __halves2bfloat162(h0, h1);
        ((__nv_bfloat162*)oh)[i*2+1] = __halves2bfloat162(h2, h3);
        ((__nv_bfloat162*)ol)[i*2]   = __halves2bfloat162(l0, l1);
        ((__nv_bfloat162*)ol)[i*2+1] = __halves2bfloat162(l2, l3);
    }
}

// ---------------------------------------------------------------------------
// split fp32 [R][C] -> transposed (hi, lo) bf16 [C][R]; batched by blockIdx.z
// ---------------------------------------------------------------------------
__global__ void __launch_bounds__(256)
split_tr(const float* __restrict__ in, bf16* __restrict__ oh,
         bf16* __restrict__ ol, int R, int C)
{
    __shared__ float t[32][33];
    const long zo = (long)blockIdx.z * R * C;
    in += zo; oh += zo; ol += zo;
    const int c0 = blockIdx.x * 32, r0 = blockIdx.y * 32;
    const int tx = threadIdx.x, ty = threadIdx.y;
#pragma unroll
    for (int i = 0; i < 4; i++)
        t[ty + i * 8][tx] = in[(long)(r0 + ty + i * 8) * C + c0 + tx];
    __syncthreads();
#pragma unroll
    for (int i = 0; i < 4; i++) {
        const float v = t[tx][ty + i * 8];
        bf16 h, l; split2(v, h, l);
        const long o = (long)(c0 + ty + i * 8) * R + r0 + tx;
        oh[o] = h; ol[o] = l;
    }
}

// ---------------------------------------------------------------------------
// masked softmax over score rows; writes split bf16 probabilities
// ---------------------------------------------------------------------------
__global__ void __launch_bounds__(256)
masked_softmax_split(const float* __restrict__ scores, const int* __restrict__ mask,
                     bf16* __restrict__ ph, bf16* __restrict__ pl)
{
    const long r = blockIdx.x;
    const int  q = (int)(r & (Ss - 1));
    const int  z = (int)(r >> 11);
    const int  b = z >> 4;
    const float* row  = scores + r * (long)Ss;
    const int*   mrow = mask + b * Ss;
    const int    mq   = mrow[q];
    const int    tid  = threadIdx.x;

    __shared__ float red_m[8];
    __shared__ float red_s[8];

    float v[8];
    float mx = -3.0e38f;
#pragma unroll
    for (int i = 0; i < 8; i++) {
        const int k = tid + i * 256;
        float s = row[k];
        if (mq == 0 || mrow[k] == 0) s = -1000000.0f;
        v[i] = s;
        mx = fmaxf(mx, s);
    }
#pragma unroll
    for (int o = 16; o > 0; o >>= 1)
        mx = fmaxf(mx, __shfl_xor_sync(0xffffffffu, mx, o));
    if ((tid & 31) == 0) red_m[tid >> 5] = mx;
    __syncthreads();
    mx = red_m[0];
#pragma unroll
    for (int i = 1; i < 8; i++) mx = fmaxf(mx, red_m[i]);

    float sum = 0.0f;
#pragma unroll
    for (int i = 0; i < 8; i++) {
        v[i] = __expf(v[i] - mx);
        sum += v[i];
    }
#pragma unroll
    for (int o = 16; o > 0; o >>= 1)
        sum += __shfl_xor_sync(0xffffffffu, sum, o);
    if ((tid & 31) == 0) red_s[tid >> 5] = sum;
    __syncthreads();
    float tot = red_s[0];
#pragma unroll
    for (int i = 1; i < 8; i++) tot += red_s[i];

    const float inv = 1.0f / tot;
#pragma unroll
    for (int i = 0; i < 8; i++) {
        const float p = v[i] * inv;
        bf16 h, l; split2(p, h, l);
        const long o = r * (long)Ss + tid + i * 256;
        ph[o] = h; pl[o] = l;
    }
}

// ---------------------------------------------------------------------------
extern "C" void kernel_launch(void* const* d_in, const int* in_sizes, int n_in,
                              void* d_out, int out_size)
{
    (void)in_sizes; (void)n_in; (void)out_size;
    const float* X   = (const float*)d_in[0];
    const int*   msk = (const int*)  d_in[1];
    const float* Wq  = (const float*)d_in[2];
    const float* Wk  = (const float*)d_in[3];
    const float* Wv  = (const float*)d_in[4];
    const float* Wqm = (const float*)d_in[5];
    const float* Wkm = (const float*)d_in[6];
    const float* Wvm = (const float*)d_in[7];
    const float* Wo  = (const float*)d_in[8];
    float* Y = (float*)d_out;

    float *Vm, *Sc;
    bf16 *tAh, *tAl, *tBh, *tBl, *WcTh, *WcTl, *Xh, *Xl;
    bf16 *Qmh, *Qml, *Kmh, *Kml, *Vth, *Vtl, *Ph, *Pl, *Atth, *Attl;
    cudaGetSymbolAddress((void**)&Vm,   g_Vm);
    cudaGetSymbolAddress((void**)&Sc,   g_Sc);
    cudaGetSymbolAddress((void**)&tAh,  g_tAh);  cudaGetSymbolAddress((void**)&tAl,  g_tAl);
    cudaGetSymbolAddress((void**)&tBh,  g_tBh);  cudaGetSymbolAddress((void**)&tBl,  g_tBl);
    cudaGetSymbolAddress((void**)&WcTh, g_WcTh); cudaGetSymbolAddress((void**)&WcTl, g_WcTl);
    cudaGetSymbolAddress((void**)&Xh,   g_Xh);   cudaGetSymbolAddress((void**)&Xl,   g_Xl);
    cudaGetSymbolAddress((void**)&Qmh,  g_Qmh);  cudaGetSymbolAddress((void**)&Qml,  g_Qml);
    cudaGetSymbolAddress((void**)&Kmh,  g_Kmh);  cudaGetSymbolAddress((void**)&Kml,  g_Kml);
    cudaGetSymbolAddress((void**)&Vth,  g_Vth);  cudaGetSymbolAddress((void**)&Vtl,  g_Vtl);
    cudaGetSymbolAddress((void**)&Ph,   g_Ph);   cudaGetSymbolAddress((void**)&Pl,   g_Pl);
    cudaGetSymbolAddress((void**)&Atth, g_Atth); cudaGetSymbolAddress((void**)&Attl, g_Attl);

    const unsigned SMB = 98304;   // 3 stages * 32KB
    cudaFuncSetAttribute(mma_nt<0>, cudaFuncAttributeMaxDynamicSharedMemorySize, SMB);
    cudaFuncSetAttribute(mma_nt<1>, cudaFuncAttributeMaxDynamicSharedMemorySize, SMB);

    const dim3 b128(128);
    const dim3 b256(256);
    const dim3 bTr(32, 8);
    const dim3 gTrW(Hh / 32, Hh / 32, 1);
    const dim3 gW(16, 16, 1);
    const dim3 gP(16, 32, 1);
    const unsigned SPW = 4096;
    const unsigned SPX = 8192;

    // split X once
    split_plain<<<SPX, b256>>>(X, Xh, Xl, 8388608 / 4);

    const float* Wt[3]  = {Wq, Wk, Wv};
    const float* Wmt[3] = {Wqm, Wkm, Wvm};
    for (int s = 0; s < 3; s++) {
        // WcT = Wm^T @ W^T via NT, split-out epilogue
        split_plain<<<SPW, b256>>>(Wt[s], tBh, tBl, 4194304 / 4);
        split_tr<<<gTrW, bTr>>>(Wmt[s], tAh, tAl, Hh, Hh);
        mma_nt<1><<<gW, b128, SMB>>>(tAh, tAl, tBh, tBl, nullptr, WcTh, WcTl,
                                     Hh, Hh, Hh, Hh, 0, 0, 0);
        // P = X @ Wc via NT (B = WcT); Q/K -> split out, V -> fp32 (needs transpose)
        if (s == 0)
            mma_nt<1><<<gP, b128, SMB>>>(Xh, Xl, WcTh, WcTl, nullptr, Qmh, Qml,
                                         Hh, Hh, Hh, Hh, 0, 0, 0);
        else if (s == 1)
            mma_nt<1><<<gP, b128, SMB>>>(Xh, Xl, WcTh, WcTl, nullptr, Kmh, Kml,
                                         Hh, Hh, Hh, Hh, 0, 0, 0);
        else
            mma_nt<0><<<gP, b128, SMB>>>(Xh, Xl, WcTh, WcTl, Vm, nullptr, nullptr,
                                         Hh, Hh, Hh, Hh, 0, 0, 0);
    }

    // per-head V^T (hi/lo)
    split_tr<<<dim3(HDim / 32, Ss / 32, NZ), bTr>>>(Vm, Vth, Vtl, Ss, HDim);

    // scores: Sc_z = Qh_z @ Kh_z^T
    mma_nt<0><<<dim3(16, 16, NZ), b128, SMB>>>(
        Qmh, Qml, Kmh, Kml, Sc, nullptr, nullptr,
        HDim, HDim, HDim, Ss,
        (long)Ss * HDim, (long)Ss * HDim, (long)Ss * Ss);

    // masked softmax + split
    masked_softmax_split<<<(unsigned)(NZ * Ss), b256>>>(Sc, msk, Ph, Pl);

    // PV: Att_z = P_z @ V_z via NT with B = V_z^T, split-out epilogue
    mma_nt<1><<<dim3(1, 16, NZ), b128, SMB>>>(
        Ph, Pl, Vth, Vtl, nullptr, Atth, Attl,
        Ss, Ss, Ss, HDim,
        (long)Ss * Ss, (long)HDim * Ss, (long)Ss * HDim);

    // final: Y = Att @ Wo via NT with B = Wo^T
    split_tr<<<gTrW, bTr>>>(Wo, tAh, tAl, Hh, Hh);
    mma_nt<0><<<gP, b128, SMB>>>(Atth, Attl, tAh, tAl, Y, nullptr, nullptr,
                                 Hh, Hh, Hh, Hh, 0, 0, 0);
}